// round 2
// baseline (speedup 1.0000x reference)
#include <cuda_runtime.h>
#include <cuda_bf16.h>
#include <math.h>

// Problem constants
#define D_MODEL 768
#define D_INNER 1536
#define N_STATE 16
#define D_CONV  4
#define DT_RANK 48
#define BB      2
#define LL      2048
#define BL      (BB*LL)        // 4096 rows
#define NCHUNK  16
#define CLEN    (LL/NCHUNK)    // 128

// -------- scratch (device globals; no allocation in kernel_launch) --------
__device__ float g_xn   [BL * D_MODEL];            // layernorm out
__device__ float g_xr   [BL * 2 * D_INNER];        // in_proj out (xin | res)
__device__ float g_xc   [BL * D_INNER];            // conv+silu out (u)
__device__ float g_dbc  [BL * (DT_RANK + 2*N_STATE)]; // x_proj out (dt|B|C), 80 cols
__device__ float g_delta[BL * D_INNER];            // softplus(dt_proj)
__device__ float g_yg   [BL * D_INNER];            // gated scan out
__device__ float g_hchunk[BB * NCHUNK * N_STATE * D_INNER]; // [b][c][n][d] local final states
__device__ float g_S     [BB * NCHUNK * D_INNER];           // [b][c][d] per-chunk sum(delta)
__device__ float g_hin   [BB * NCHUNK * N_STATE * D_INNER]; // [b][c][n][d] chunk initial states

// ---------------- LayerNorm ----------------
__device__ __forceinline__ float block_sum_768(float v, float* sh) {
    int lane = threadIdx.x & 31, w = threadIdx.x >> 5;
    #pragma unroll
    for (int o = 16; o > 0; o >>= 1) v += __shfl_xor_sync(0xffffffffu, v, o);
    if (lane == 0) sh[w] = v;
    __syncthreads();
    if (threadIdx.x == 0) {
        float s = 0.f;
        #pragma unroll
        for (int i = 0; i < 8; i++) s += sh[i];
        sh[8] = s;
    }
    __syncthreads();
    float r = sh[8];
    __syncthreads();
    return r;
}

__global__ __launch_bounds__(256) void ln_kernel(const float* __restrict__ x,
                                                 const float* __restrict__ w,
                                                 const float* __restrict__ b) {
    __shared__ float sh[9];
    int row = blockIdx.x;
    const float* xp = x + (size_t)row * D_MODEL;
    int t = threadIdx.x;
    float v0 = xp[t], v1 = xp[t + 256], v2 = xp[t + 512];
    float mu = block_sum_768(v0 + v1 + v2, sh) * (1.f / 768.f);
    float d0 = v0 - mu, d1 = v1 - mu, d2 = v2 - mu;
    float var = block_sum_768(d0*d0 + d1*d1 + d2*d2, sh) * (1.f / 768.f);
    float inv = rsqrtf(var + 1e-5f);
    float* o = g_xn + (size_t)row * D_MODEL;
    o[t]       = d0 * inv * w[t]       + b[t];
    o[t + 256] = d1 * inv * w[t + 256] + b[t + 256];
    o[t + 512] = d2 * inv * w[t + 512] + b[t + 512];
}

// ---------------- Big NT GEMM: C[M][N] = A[M][K] * B[N][K]^T ----------------
// BM=BN=128, BK=16, 256 threads, 8x8 per thread, register-staged double buffer.
// Requires M%128==0, N%128==0, K%16==0.
// EPI: 0 = none, 1 = +bias then softplus
template<int EPI>
__global__ __launch_bounds__(256) void gemm128(const float* __restrict__ A, int lda,
                                               const float* __restrict__ B, int ldb,
                                               float* __restrict__ C, int ldc,
                                               int K, const float* __restrict__ bias) {
    __shared__ float As[16][132];
    __shared__ float Bs[16][132];
    const int m0 = blockIdx.y * 128;
    const int n0 = blockIdx.x * 128;
    const int tid = threadIdx.x;
    const int lm = tid >> 1;          // 0..127 row within tile
    const int lk = (tid & 1) * 8;     // 0 or 8 (each thread loads 8 consecutive k)
    const int ty = tid >> 4;          // 0..15 (m)
    const int tx = tid & 15;          // 0..15 (n)

    float acc[8][8];
    #pragma unroll
    for (int i = 0; i < 8; i++)
        #pragma unroll
        for (int j = 0; j < 8; j++) acc[i][j] = 0.f;

    const float* Aptr = A + (size_t)(m0 + lm) * lda + lk;
    const float* Bptr = B + (size_t)(n0 + lm) * ldb + lk;

    // prefetch tile 0 into registers
    float4 av0 = *(const float4*)(Aptr);
    float4 av1 = *(const float4*)(Aptr + 4);
    float4 bv0 = *(const float4*)(Bptr);
    float4 bv1 = *(const float4*)(Bptr + 4);

    for (int k0 = 0; k0 < K; k0 += 16) {
        __syncthreads();   // prior compute done reading smem
        As[lk + 0][lm] = av0.x; As[lk + 1][lm] = av0.y;
        As[lk + 2][lm] = av0.z; As[lk + 3][lm] = av0.w;
        As[lk + 4][lm] = av1.x; As[lk + 5][lm] = av1.y;
        As[lk + 6][lm] = av1.z; As[lk + 7][lm] = av1.w;
        Bs[lk + 0][lm] = bv0.x; Bs[lk + 1][lm] = bv0.y;
        Bs[lk + 2][lm] = bv0.z; Bs[lk + 3][lm] = bv0.w;
        Bs[lk + 4][lm] = bv1.x; Bs[lk + 5][lm] = bv1.y;
        Bs[lk + 6][lm] = bv1.z; Bs[lk + 7][lm] = bv1.w;
        __syncthreads();
        // issue next tile's global loads; latency hidden behind 1024 FFMAs below
        if (k0 + 16 < K) {
            av0 = *(const float4*)(Aptr + k0 + 16);
            av1 = *(const float4*)(Aptr + k0 + 20);
            bv0 = *(const float4*)(Bptr + k0 + 16);
            bv1 = *(const float4*)(Bptr + k0 + 20);
        }
        #pragma unroll
        for (int kk = 0; kk < 16; kk++) {
            float a[8], bb[8];
            *(float4*)(a)      = *(const float4*)(&As[kk][ty * 8]);
            *(float4*)(a + 4)  = *(const float4*)(&As[kk][ty * 8 + 4]);
            *(float4*)(bb)     = *(const float4*)(&Bs[kk][tx * 8]);
            *(float4*)(bb + 4) = *(const float4*)(&Bs[kk][tx * 8 + 4]);
            #pragma unroll
            for (int i = 0; i < 8; i++)
                #pragma unroll
                for (int j = 0; j < 8; j++)
                    acc[i][j] += a[i] * bb[j];
        }
    }

    #pragma unroll
    for (int i = 0; i < 8; i++) {
        int row = m0 + ty * 8 + i;
        float* Crow = C + (size_t)row * ldc + n0 + tx * 8;
        #pragma unroll
        for (int j = 0; j < 8; j++) {
            float v = acc[i][j];
            if (EPI == 1) {
                v += bias[n0 + tx * 8 + j];
                v = (v > 20.f) ? v : log1pf(__expf(v));
            }
            Crow[j] = v;
        }
    }
}

// ---------------- Small NT GEMM for x_proj (N=80): BM=64, BN=16, BK=16 ----------------
__global__ __launch_bounds__(256) void gemm_small(const float* __restrict__ A, int lda,
                                                  const float* __restrict__ B, int ldb,
                                                  float* __restrict__ C, int ldc, int K) {
    __shared__ float As[16][68];
    __shared__ float Bs[16][17];
    const int m0 = blockIdx.y * 64;
    const int n0 = blockIdx.x * 16;
    const int tid = threadIdx.x;
    const int am = tid >> 2, ak = (tid & 3) * 4;
    const int bn = tid >> 4, bk = tid & 15;
    const int ty = tid >> 4, tx = tid & 15;

    float acc[4] = {0.f, 0.f, 0.f, 0.f};
    float4 av = *(const float4*)(A + (size_t)(m0 + am) * lda + ak);
    float bvv = B[(size_t)(n0 + bn) * ldb + bk];
    for (int k0 = 0; k0 < K; k0 += 16) {
        __syncthreads();
        As[ak + 0][am] = av.x; As[ak + 1][am] = av.y;
        As[ak + 2][am] = av.z; As[ak + 3][am] = av.w;
        Bs[bk][bn] = bvv;
        __syncthreads();
        if (k0 + 16 < K) {
            av = *(const float4*)(A + (size_t)(m0 + am) * lda + k0 + 16 + ak);
            bvv = B[(size_t)(n0 + bn) * ldb + k0 + 16 + bk];
        }
        #pragma unroll
        for (int kk = 0; kk < 16; kk++) {
            float4 a = *(const float4*)(&As[kk][ty * 4]);
            float bbv = Bs[kk][tx];
            acc[0] += a.x * bbv; acc[1] += a.y * bbv;
            acc[2] += a.z * bbv; acc[3] += a.w * bbv;
        }
    }
    #pragma unroll
    for (int i = 0; i < 4; i++)
        C[(size_t)(m0 + ty * 4 + i) * ldc + n0 + tx] = acc[i];
}

// ---------------- depthwise causal conv(k=4) + bias + SiLU ----------------
__global__ __launch_bounds__(256) void conv_silu_kernel(const float* __restrict__ w,
                                                        const float* __restrict__ cb) {
    int idx = blockIdx.x * 256 + threadIdx.x;   // over BL*D_INNER
    int d = idx % D_INNER;
    int row = idx / D_INNER;                    // b*LL + l
    int l = row & (LL - 1);
    const float* xin = g_xr + (size_t)row * (2 * D_INNER) + d;  // col d of xin half
    float acc = cb[d];
    float4 wv = *(const float4*)(w + d * 4);
    if (l >= 3) acc += wv.x * xin[-3 * 2 * D_INNER];
    if (l >= 2) acc += wv.y * xin[-2 * 2 * D_INNER];
    if (l >= 1) acc += wv.z * xin[-1 * 2 * D_INNER];
    acc += wv.w * xin[0];
    g_xc[(size_t)row * D_INNER + d] = __fdividef(acc, 1.f + __expf(-acc));  // silu
}

// ---------------- selective scan (chunked, 3 passes) ----------------
// pass1: per (b,chunk,d) local scan from h=0; emits h_final[16], S=sum(delta)
__global__ __launch_bounds__(128) void scan_pass1(const float* __restrict__ A_log) {
    __shared__ float sB[CLEN * N_STATE];
    int c = blockIdx.x, b = blockIdx.y;
    int d = blockIdx.z * 128 + threadIdx.x;
    int rowbase = b * LL + c * CLEN;
    for (int i = threadIdx.x; i < CLEN * N_STATE; i += 128) {
        int l = i >> 4, n = i & 15;
        sB[i] = g_dbc[(size_t)(rowbase + l) * 80 + DT_RANK + n];
    }
    __syncthreads();
    float Areg[N_STATE];
    #pragma unroll
    for (int n = 0; n < N_STATE; n++) Areg[n] = -__expf(A_log[d * N_STATE + n]);
    float h[N_STATE];
    #pragma unroll
    for (int n = 0; n < N_STATE; n++) h[n] = 0.f;
    float S = 0.f;
    for (int l = 0; l < CLEN; l++) {
        size_t off = (size_t)(rowbase + l) * D_INNER + d;
        float dl = g_delta[off];
        float ul = g_xc[off];
        S += dl;
        float du = dl * ul;
        const float* bl = sB + l * N_STATE;
        #pragma unroll
        for (int n = 0; n < N_STATE; n++)
            h[n] = __expf(dl * Areg[n]) * h[n] + du * bl[n];
    }
    size_t base = (size_t)((b * NCHUNK + c) * N_STATE) * D_INNER + d;
    #pragma unroll
    for (int n = 0; n < N_STATE; n++) g_hchunk[base + (size_t)n * D_INNER] = h[n];
    g_S[(size_t)(b * NCHUNK + c) * D_INNER + d] = S;
}

// pass2: sequential over chunks; h_in[c] from h_in[c-1] via exp(A*S)*h + h_final
__global__ __launch_bounds__(256) void scan_pass2(const float* __restrict__ A_log) {
    int d = blockIdx.x * 256 + threadIdx.x;
    int b = blockIdx.y;
    float Areg[N_STATE];
    #pragma unroll
    for (int n = 0; n < N_STATE; n++) Areg[n] = -__expf(A_log[d * N_STATE + n]);
    float h[N_STATE];
    #pragma unroll
    for (int n = 0; n < N_STATE; n++) h[n] = 0.f;
    for (int c = 0; c < NCHUNK; c++) {
        size_t base = (size_t)((b * NCHUNK + c) * N_STATE) * D_INNER + d;
        #pragma unroll
        for (int n = 0; n < N_STATE; n++) g_hin[base + (size_t)n * D_INNER] = h[n];
        float S = g_S[(size_t)(b * NCHUNK + c) * D_INNER + d];
        #pragma unroll
        for (int n = 0; n < N_STATE; n++)
            h[n] = __expf(S * Areg[n]) * h[n] + g_hchunk[base + (size_t)n * D_INNER];
    }
}

// pass3: replay with correct h_in, produce y = scan + u*D, gated by silu(res)
__global__ __launch_bounds__(128) void scan_pass3(const float* __restrict__ A_log,
                                                  const float* __restrict__ Dp) {
    __shared__ float sBC[CLEN * 2 * N_STATE];
    int c = blockIdx.x, b = blockIdx.y;
    int d = blockIdx.z * 128 + threadIdx.x;
    int rowbase = b * LL + c * CLEN;
    for (int i = threadIdx.x; i < CLEN * 2 * N_STATE; i += 128) {
        int l = i >> 5, j = i & 31;
        sBC[i] = g_dbc[(size_t)(rowbase + l) * 80 + DT_RANK + j]; // cols 48..79 = B|C
    }
    __syncthreads();
    float Areg[N_STATE];
    #pragma unroll
    for (int n = 0; n < N_STATE; n++) Areg[n] = -__expf(A_log[d * N_STATE + n]);
    float h[N_STATE];
    size_t hbase = (size_t)((b * NCHUNK + c) * N_STATE) * D_INNER + d;
    #pragma unroll
    for (int n = 0; n < N_STATE; n++) h[n] = g_hin[hbase + (size_t)n * D_INNER];
    float Dd = Dp[d];
    for (int l = 0; l < CLEN; l++) {
        size_t off = (size_t)(rowbase + l) * D_INNER + d;
        float dl = g_delta[off];
        float ul = g_xc[off];
        float du = dl * ul;
        const float* bl = sBC + l * 2 * N_STATE;
        float y = 0.f;
        #pragma unroll
        for (int n = 0; n < N_STATE; n++) {
            h[n] = __expf(dl * Areg[n]) * h[n] + du * bl[n];
            y += h[n] * bl[N_STATE + n];
        }
        y += ul * Dd;
        int row = rowbase + l;
        float r = g_xr[(size_t)row * (2 * D_INNER) + D_INNER + d];  // res
        float sr = __fdividef(r, 1.f + __expf(-r));                 // silu(res)
        g_yg[off] = y * sr;
    }
}

// ---------------- launch ----------------
extern "C" void kernel_launch(void* const* d_in, const int* in_sizes, int n_in,
                              void* d_out, int out_size) {
    const float* x      = (const float*)d_in[0];
    const float* ln_w   = (const float*)d_in[1];
    const float* ln_b   = (const float*)d_in[2];
    const float* in_w   = (const float*)d_in[3];   // (3072, 768)
    const float* conv_w = (const float*)d_in[4];   // (1536, 1, 4)
    const float* conv_b = (const float*)d_in[5];
    const float* xp_w   = (const float*)d_in[6];   // (80, 1536)
    const float* dt_w   = (const float*)d_in[7];   // (1536, 48)
    const float* dt_b   = (const float*)d_in[8];
    const float* A_log  = (const float*)d_in[9];   // (1536, 16)
    const float* Dp     = (const float*)d_in[10];  // (1536,)
    const float* out_w  = (const float*)d_in[11];  // (768, 1536)
    float* out = (float*)d_out;

    float *xn, *xr, *xc, *dbc, *delta, *yg;
    cudaGetSymbolAddress((void**)&xn,    g_xn);
    cudaGetSymbolAddress((void**)&xr,    g_xr);
    cudaGetSymbolAddress((void**)&xc,    g_xc);
    cudaGetSymbolAddress((void**)&dbc,   g_dbc);
    cudaGetSymbolAddress((void**)&delta, g_delta);
    cudaGetSymbolAddress((void**)&yg,    g_yg);

    // 1. LayerNorm
    ln_kernel<<<BL, 256>>>(x, ln_w, ln_b);
    // 2. in_proj: (4096x768) @ (3072x768)^T -> (4096x3072)
    gemm128<0><<<dim3(2 * D_INNER / 128, BL / 128), 256>>>(xn, D_MODEL, in_w, D_MODEL,
                                                           xr, 2 * D_INNER, D_MODEL, nullptr);
    // 3. depthwise conv + SiLU -> u
    conv_silu_kernel<<<(BL * D_INNER) / 256, 256>>>(conv_w, conv_b);
    // 4. x_proj: (4096x1536) @ (80x1536)^T -> (4096x80)
    gemm_small<<<dim3(80 / 16, BL / 64), 256>>>(xc, D_INNER, xp_w, D_INNER, dbc, 80, D_INNER);
    // 5. dt_proj + bias + softplus: (4096x48) @ (1536x48)^T -> (4096x1536)
    gemm128<1><<<dim3(D_INNER / 128, BL / 128), 256>>>(dbc, 80, dt_w, DT_RANK,
                                                       delta, D_INNER, DT_RANK, dt_b);
    // 6-8. chunked selective scan + gate
    scan_pass1<<<dim3(NCHUNK, BB, D_INNER / 128), 128>>>(A_log);
    scan_pass2<<<dim3(D_INNER / 256, BB), 256>>>(A_log);
    scan_pass3<<<dim3(NCHUNK, BB, D_INNER / 128), 128>>>(A_log, Dp);
    // 9. out_proj: (4096x1536) @ (768x1536)^T -> (4096x768)
    gemm128<0><<<dim3(D_MODEL / 128, BL / 128), 256>>>(yg, D_INNER, out_w, D_INNER,
                                                       out, D_MODEL, D_INNER, nullptr);
}

// round 14
// speedup vs baseline: 1.4839x; 1.4839x over previous
#include <cuda_runtime.h>
#include <cuda_bf16.h>
#include <math.h>
#include <stdint.h>

// Problem constants
#define D_MODEL 768
#define D_INNER 1536
#define N_STATE 16
#define D_CONV  4
#define DT_RANK 48
#define BB      2
#define LL      2048
#define BL      (BB*LL)        // 4096 rows
#define NCHUNK  16
#define CLEN    (LL/NCHUNK)    // 128

__device__ __forceinline__ uint32_t smem_to_u32(const void* p) {
    uint32_t a;
    asm("{ .reg .u64 t; cvta.to.shared.u64 t, %1; cvt.u32.u64 %0, t; }" : "=r"(a) : "l"(p));
    return a;
}
__device__ __forceinline__ void ldsm_x4(uint32_t& r0, uint32_t& r1, uint32_t& r2, uint32_t& r3,
                                        uint32_t addr) {
    asm volatile("ldmatrix.sync.aligned.m8n8.x4.shared.b16 {%0,%1,%2,%3}, [%4];"
                 : "=r"(r0), "=r"(r1), "=r"(r2), "=r"(r3) : "r"(addr));
}
__device__ __forceinline__ void mma_bf16(float* c, const uint32_t* a, const uint32_t* b) {
    asm volatile("mma.sync.aligned.m16n8k16.row.col.f32.bf16.bf16.f32 "
                 "{%0,%1,%2,%3}, {%4,%5,%6,%7}, {%8,%9}, {%0,%1,%2,%3};"
                 : "+f"(c[0]), "+f"(c[1]), "+f"(c[2]), "+f"(c[3])
                 : "r"(a[0]), "r"(a[1]), "r"(a[2]), "r"(a[3]), "r"(b[0]), "r"(b[1]));
}

// -------- scratch (device globals; no allocation anywhere) --------
__device__ float g_xr   [BL * 2 * D_INNER];          // in_proj out (xin | res) fp32
__device__ float g_xc   [BL * D_INNER];              // conv+silu out u (fp32, for scan)
__device__ float g_dbc  [BL * 80];                   // x_proj out (dt|B|C) fp32
__device__ float g_delta[BL * D_INNER];              // softplus(dt_proj)
__device__ float g_hchunk[BB * NCHUNK * N_STATE * D_INNER];
__device__ float g_S     [BB * NCHUNK * D_INNER];
__device__ float g_hin   [BB * NCHUNK * N_STATE * D_INNER];
// bf16 hi/lo operand buffers (16B aligned for vectorized loads)
__device__ __align__(16) __nv_bfloat16 g_xn_h[BL * D_MODEL],   g_xn_l[BL * D_MODEL];
__device__ __align__(16) __nv_bfloat16 g_u_h [BL * D_INNER],   g_u_l [BL * D_INNER];
__device__ __align__(16) __nv_bfloat16 g_yg_h[BL * D_INNER],   g_yg_l[BL * D_INNER];
__device__ __align__(16) __nv_bfloat16 g_dti_h[BL * 64],       g_dti_l[BL * 64];
__device__ __align__(16) __nv_bfloat16 g_inw_h[2*D_INNER*D_MODEL], g_inw_l[2*D_INNER*D_MODEL];
__device__ __align__(16) __nv_bfloat16 g_xpw_h[80*D_INNER],    g_xpw_l[80*D_INNER];
__device__ __align__(16) __nv_bfloat16 g_dtw_h[D_INNER*64],    g_dtw_l[D_INNER*64];
__device__ __align__(16) __nv_bfloat16 g_outw_h[D_MODEL*D_INNER], g_outw_l[D_MODEL*D_INNER];

__device__ __forceinline__ void f32_hl(float x, __nv_bfloat16& h, __nv_bfloat16& l) {
    h = __float2bfloat16(x);
    l = __float2bfloat16(x - __bfloat162float(h));
}

// ---------------- mma.sync bf16 GEMM: C = A·B^T, 3-term compensation ----------------
// BM=BN=128, BK=32; 256 threads = 8 warps (4 m × 2 n); warp tile 32x64.
// A:[M][K] (Ah,Al) row-major; B:[N][K] (Bh,Bl); rows >= Nvalid zero-filled.
#define TSTRIDE 40   // 32 + 8 pad (bf16 elems per smem row)

__device__ __forceinline__ void load_tile32(__nv_bfloat16* dst,
                                            const __nv_bfloat16* __restrict__ src,
                                            int ld, int row0, int maxrow, int kc, int tid) {
    #pragma unroll
    for (int it = 0; it < 2; it++) {
        int idx = it * 256 + tid;        // 0..511
        int r = idx >> 2, ch = idx & 3;  // row 0..127, 8-half chunk 0..3
        uint4 v = make_uint4(0u, 0u, 0u, 0u);
        if (row0 + r < maxrow)
            v = *(const uint4*)(src + (size_t)(row0 + r) * ld + kc + ch * 8);
        *(uint4*)(dst + r * TSTRIDE + ch * 8) = v;
    }
}

template<int EPI>   // 0: none, 1: +bias then softplus
__global__ __launch_bounds__(256, 1) void tgemm(const __nv_bfloat16* __restrict__ Ah,
                                                const __nv_bfloat16* __restrict__ Al,
                                                const __nv_bfloat16* __restrict__ Bh,
                                                const __nv_bfloat16* __restrict__ Bl,
                                                float* __restrict__ C, int ldc,
                                                int K, int Nvalid,
                                                const float* __restrict__ bias) {
    __shared__ __nv_bfloat16 sAh[128 * TSTRIDE], sAl[128 * TSTRIDE];
    __shared__ __nv_bfloat16 sBh[128 * TSTRIDE], sBl[128 * TSTRIDE];
    const int tid = threadIdx.x;
    const int lane = tid & 31, wid = tid >> 5;
    const int warp_m = wid >> 1;          // 0..3 -> 32-row slab
    const int warp_n = wid & 1;           // 0..1 -> 64-col slab
    const int m0 = blockIdx.y * 128;
    const int n0 = blockIdx.x * 128;

    const uint32_t bAh = smem_to_u32(sAh), bAl = smem_to_u32(sAl);
    const uint32_t bBh = smem_to_u32(sBh), bBl = smem_to_u32(sBl);

    // ldmatrix per-thread source coordinates
    const int a_row = lane & 15;                 // row within 16-row tile
    const int a_kx  = (lane >> 4);               // 0/1 -> k-subblock (8 halves)
    const int b_row = (lane & 7) + ((lane >> 4) << 3);  // n within 16-col pair
    const int b_kx  = (lane >> 3) & 1;

    float acc[2][8][4];
    #pragma unroll
    for (int mt = 0; mt < 2; mt++)
        #pragma unroll
        for (int nt = 0; nt < 8; nt++)
            #pragma unroll
            for (int i = 0; i < 4; i++) acc[mt][nt][i] = 0.f;

    for (int kc = 0; kc < K; kc += 32) {
        __syncthreads();
        load_tile32(sAh, Ah, K, m0, 1 << 30, kc, tid);
        load_tile32(sAl, Al, K, m0, 1 << 30, kc, tid);
        load_tile32(sBh, Bh, K, n0, Nvalid, kc, tid);
        load_tile32(sBl, Bl, K, n0, Nvalid, kc, tid);
        __syncthreads();

        #pragma unroll
        for (int ks = 0; ks < 2; ks++) {
            const int kbase = ks * 16;
            uint32_t ah[2][4], al[2][4];
            #pragma unroll
            for (int mt = 0; mt < 2; mt++) {
                uint32_t off = (uint32_t)(((warp_m * 32 + mt * 16 + a_row) * TSTRIDE
                                           + kbase + a_kx * 8) * 2);
                ldsm_x4(ah[mt][0], ah[mt][1], ah[mt][2], ah[mt][3], bAh + off);
                ldsm_x4(al[mt][0], al[mt][1], al[mt][2], al[mt][3], bAl + off);
            }
            uint32_t bh[8][2], bl[8][2];
            #pragma unroll
            for (int ntp = 0; ntp < 4; ntp++) {   // n-tile pairs (16 cols each)
                uint32_t off = (uint32_t)(((warp_n * 64 + ntp * 16 + b_row) * TSTRIDE
                                           + kbase + b_kx * 8) * 2);
                ldsm_x4(bh[2*ntp][0], bh[2*ntp][1], bh[2*ntp+1][0], bh[2*ntp+1][1], bBh + off);
                ldsm_x4(bl[2*ntp][0], bl[2*ntp][1], bl[2*ntp+1][0], bl[2*ntp+1][1], bBl + off);
            }
            #pragma unroll
            for (int mt = 0; mt < 2; mt++)
                #pragma unroll
                for (int nt = 0; nt < 8; nt++) {
                    mma_bf16(acc[mt][nt], ah[mt], bh[nt]);
                    mma_bf16(acc[mt][nt], ah[mt], bl[nt]);
                    mma_bf16(acc[mt][nt], al[mt], bh[nt]);
                }
        }
    }

    // Epilogue: fragment layout c0,c1=(r, 2c/2c+1), c2,c3=(r+8, ...)
    const int r_off = lane >> 2;
    const int c_off = (lane & 3) * 2;
    #pragma unroll
    for (int mt = 0; mt < 2; mt++) {
        #pragma unroll
        for (int nt = 0; nt < 8; nt++) {
            int row_g = m0 + warp_m * 32 + mt * 16 + r_off;
            int col_g = n0 + warp_n * 64 + nt * 8 + c_off;
            if (col_g < Nvalid) {
                float v0 = acc[mt][nt][0], v1 = acc[mt][nt][1];
                float v2 = acc[mt][nt][2], v3 = acc[mt][nt][3];
                if (EPI == 1) {
                    float bv0 = bias[col_g], bv1 = bias[col_g + 1];
                    v0 += bv0; v1 += bv1; v2 += bv0; v3 += bv1;
                    v0 = (v0 > 20.f) ? v0 : log1pf(__expf(v0));
                    v1 = (v1 > 20.f) ? v1 : log1pf(__expf(v1));
                    v2 = (v2 > 20.f) ? v2 : log1pf(__expf(v2));
                    v3 = (v3 > 20.f) ? v3 : log1pf(__expf(v3));
                }
                *(float2*)(C + (size_t)row_g * ldc + col_g)       = make_float2(v0, v1);
                *(float2*)(C + (size_t)(row_g + 8) * ldc + col_g) = make_float2(v2, v3);
            }
        }
    }
}

// ---------------- LayerNorm -> bf16 hi/lo ----------------
__device__ __forceinline__ float block_sum_768(float v, float* sh) {
    int lane = threadIdx.x & 31, w = threadIdx.x >> 5;
    #pragma unroll
    for (int o = 16; o > 0; o >>= 1) v += __shfl_xor_sync(0xffffffffu, v, o);
    if (lane == 0) sh[w] = v;
    __syncthreads();
    if (threadIdx.x == 0) {
        float s = 0.f;
        #pragma unroll
        for (int i = 0; i < 8; i++) s += sh[i];
        sh[8] = s;
    }
    __syncthreads();
    float r = sh[8];
    __syncthreads();
    return r;
}

__global__ __launch_bounds__(256) void ln_kernel(const float* __restrict__ x,
                                                 const float* __restrict__ w,
                                                 const float* __restrict__ b) {
    __shared__ float sh[9];
    int row = blockIdx.x;
    const float* xp = x + (size_t)row * D_MODEL;
    int t = threadIdx.x;
    float v0 = xp[t], v1 = xp[t + 256], v2 = xp[t + 512];
    float mu = block_sum_768(v0 + v1 + v2, sh) * (1.f / 768.f);
    float d0 = v0 - mu, d1 = v1 - mu, d2 = v2 - mu;
    float var = block_sum_768(d0*d0 + d1*d1 + d2*d2, sh) * (1.f / 768.f);
    float inv = rsqrtf(var + 1e-5f);
    size_t o = (size_t)row * D_MODEL;
    #pragma unroll
    for (int j = 0; j < 3; j++) {
        int c = t + j * 256;
        float dv = (j == 0 ? d0 : (j == 1 ? d1 : d2));
        float v = dv * inv * w[c] + b[c];
        f32_hl(v, g_xn_h[o + c], g_xn_l[o + c]);
    }
}

// ---------------- fp32 -> bf16 hi/lo (generic, for weights) ----------------
__global__ __launch_bounds__(256) void conv_hl(const float* __restrict__ src,
                                               __nv_bfloat16* __restrict__ dh,
                                               __nv_bfloat16* __restrict__ dl, int n) {
    int i = blockIdx.x * 256 + threadIdx.x;
    if (i < n) f32_hl(src[i], dh[i], dl[i]);
}

// dt input: g_dbc cols 0..47 -> [BL][64] hi/lo, cols 48..63 zero
__global__ __launch_bounds__(256) void conv_dti() {
    int i = blockIdx.x * 256 + threadIdx.x;   // over BL*64
    int r = i >> 6, c = i & 63;
    float v = (c < DT_RANK) ? g_dbc[r * 80 + c] : 0.f;
    f32_hl(v, g_dti_h[i], g_dti_l[i]);
}
// dt_w: [1536][48] -> [1536][64] hi/lo padded
__global__ __launch_bounds__(256) void conv_dtw(const float* __restrict__ w) {
    int i = blockIdx.x * 256 + threadIdx.x;   // over 1536*64
    int r = i >> 6, c = i & 63;
    float v = (c < DT_RANK) ? w[r * DT_RANK + c] : 0.f;
    f32_hl(v, g_dtw_h[i], g_dtw_l[i]);
}

// ---------------- depthwise causal conv(k=4) + bias + SiLU -> u fp32 + hi/lo ----------------
__global__ __launch_bounds__(256) void conv_silu_kernel(const float* __restrict__ w,
                                                        const float* __restrict__ cb) {
    int idx = blockIdx.x * 256 + threadIdx.x;   // over BL*D_INNER
    int d = idx % D_INNER;
    int row = idx / D_INNER;
    int l = row & (LL - 1);
    const float* xin = g_xr + (size_t)row * (2 * D_INNER) + d;
    float acc = cb[d];
    float4 wv = *(const float4*)(w + d * 4);
    if (l >= 3) acc += wv.x * xin[-3 * 2 * D_INNER];
    if (l >= 2) acc += wv.y * xin[-2 * 2 * D_INNER];
    if (l >= 1) acc += wv.z * xin[-1 * 2 * D_INNER];
    acc += wv.w * xin[0];
    float u = __fdividef(acc, 1.f + __expf(-acc));
    size_t o = (size_t)row * D_INNER + d;
    g_xc[o] = u;
    f32_hl(u, g_u_h[o], g_u_l[o]);
}

// ---------------- selective scan (chunked, 3 passes) ----------------
__global__ __launch_bounds__(128) void scan_pass1(const float* __restrict__ A_log) {
    __shared__ float sB[CLEN * N_STATE];
    int c = blockIdx.x, b = blockIdx.y;
    int d = blockIdx.z * 128 + threadIdx.x;
    int rowbase = b * LL + c * CLEN;
    for (int i = threadIdx.x; i < CLEN * N_STATE; i += 128) {
        int l = i >> 4, n = i & 15;
        sB[i] = g_dbc[(size_t)(rowbase + l) * 80 + DT_RANK + n];
    }
    __syncthreads();
    float Areg[N_STATE];
    #pragma unroll
    for (int n = 0; n < N_STATE; n++) Areg[n] = -__expf(A_log[d * N_STATE + n]);
    float h[N_STATE];
    #pragma unroll
    for (int n = 0; n < N_STATE; n++) h[n] = 0.f;
    float S = 0.f;
    for (int l = 0; l < CLEN; l++) {
        size_t off = (size_t)(rowbase + l) * D_INNER + d;
        float dl = g_delta[off];
        float ul = g_xc[off];
        S += dl;
        float du = dl * ul;
        const float* bl = sB + l * N_STATE;
        #pragma unroll
        for (int n = 0; n < N_STATE; n++)
            h[n] = __expf(dl * Areg[n]) * h[n] + du * bl[n];
    }
    size_t base = (size_t)((b * NCHUNK + c) * N_STATE) * D_INNER + d;
    #pragma unroll
    for (int n = 0; n < N_STATE; n++) g_hchunk[base + (size_t)n * D_INNER] = h[n];
    g_S[(size_t)(b * NCHUNK + c) * D_INNER + d] = S;
}

__global__ __launch_bounds__(256) void scan_pass2(const float* __restrict__ A_log) {
    int d = blockIdx.x * 256 + threadIdx.x;
    int b = blockIdx.y;
    float Areg[N_STATE];
    #pragma unroll
    for (int n = 0; n < N_STATE; n++) Areg[n] = -__expf(A_log[d * N_STATE + n]);
    float h[N_STATE];
    #pragma unroll
    for (int n = 0; n < N_STATE; n++) h[n] = 0.f;
    for (int c = 0; c < NCHUNK; c++) {
        size_t base = (size_t)((b * NCHUNK + c) * N_STATE) * D_INNER + d;
        #pragma unroll
        for (int n = 0; n < N_STATE; n++) g_hin[base + (size_t)n * D_INNER] = h[n];
        float S = g_S[(size_t)(b * NCHUNK + c) * D_INNER + d];
        #pragma unroll
        for (int n = 0; n < N_STATE; n++)
            h[n] = __expf(S * Areg[n]) * h[n] + g_hchunk[base + (size_t)n * D_INNER];
    }
}

__global__ __launch_bounds__(128) void scan_pass3(const float* __restrict__ A_log,
                                                  const float* __restrict__ Dp) {
    __shared__ float sBC[CLEN * 2 * N_STATE];
    int c = blockIdx.x, b = blockIdx.y;
    int d = blockIdx.z * 128 + threadIdx.x;
    int rowbase = b * LL + c * CLEN;
    for (int i = threadIdx.x; i < CLEN * 2 * N_STATE; i += 128) {
        int l = i >> 5, j = i & 31;
        sBC[i] = g_dbc[(size_t)(rowbase + l) * 80 + DT_RANK + j];
    }
    __syncthreads();
    float Areg[N_STATE];
    #pragma unroll
    for (int n = 0; n < N_STATE; n++) Areg[n] = -__expf(A_log[d * N_STATE + n]);
    float h[N_STATE];
    size_t hbase = (size_t)((b * NCHUNK + c) * N_STATE) * D_INNER + d;
    #pragma unroll
    for (int n = 0; n < N_STATE; n++) h[n] = g_hin[hbase + (size_t)n * D_INNER];
    float Dd = Dp[d];
    for (int l = 0; l < CLEN; l++) {
        size_t off = (size_t)(rowbase + l) * D_INNER + d;
        float dl = g_delta[off];
        float ul = g_xc[off];
        float du = dl * ul;
        const float* bl = sBC + l * 2 * N_STATE;
        float y = 0.f;
        #pragma unroll
        for (int n = 0; n < N_STATE; n++) {
            h[n] = __expf(dl * Areg[n]) * h[n] + du * bl[n];
            y += h[n] * bl[N_STATE + n];
        }
        y += ul * Dd;
        int row = rowbase + l;
        float r = g_xr[(size_t)row * (2 * D_INNER) + D_INNER + d];
        float sr = __fdividef(r, 1.f + __expf(-r));
        f32_hl(y * sr, g_yg_h[off], g_yg_l[off]);
    }
}

// ---------------- launch ----------------
extern "C" void kernel_launch(void* const* d_in, const int* in_sizes, int n_in,
                              void* d_out, int out_size) {
    const float* x      = (const float*)d_in[0];
    const float* ln_w   = (const float*)d_in[1];
    const float* ln_b   = (const float*)d_in[2];
    const float* in_w   = (const float*)d_in[3];   // (3072, 768)
    const float* conv_w = (const float*)d_in[4];
    const float* conv_b = (const float*)d_in[5];
    const float* xp_w   = (const float*)d_in[6];   // (80, 1536)
    const float* dt_w   = (const float*)d_in[7];   // (1536, 48)
    const float* dt_b   = (const float*)d_in[8];
    const float* A_log  = (const float*)d_in[9];
    const float* Dp     = (const float*)d_in[10];
    const float* out_w  = (const float*)d_in[11];  // (768, 1536)
    float* out = (float*)d_out;

    float *xr, *dbc, *delta;
    __nv_bfloat16 *xnh, *xnl, *uh, *ul, *ygh, *ygl, *dtih, *dtil;
    __nv_bfloat16 *inwh, *inwl, *xpwh, *xpwl, *outwh, *outwl, *dtwh, *dtwl;
    cudaGetSymbolAddress((void**)&xr,    g_xr);
    cudaGetSymbolAddress((void**)&dbc,   g_dbc);
    cudaGetSymbolAddress((void**)&delta, g_delta);
    cudaGetSymbolAddress((void**)&xnh,   g_xn_h);  cudaGetSymbolAddress((void**)&xnl, g_xn_l);
    cudaGetSymbolAddress((void**)&uh,    g_u_h);   cudaGetSymbolAddress((void**)&ul,  g_u_l);
    cudaGetSymbolAddress((void**)&ygh,   g_yg_h);  cudaGetSymbolAddress((void**)&ygl, g_yg_l);
    cudaGetSymbolAddress((void**)&dtih,  g_dti_h); cudaGetSymbolAddress((void**)&dtil, g_dti_l);
    cudaGetSymbolAddress((void**)&inwh,  g_inw_h); cudaGetSymbolAddress((void**)&inwl, g_inw_l);
    cudaGetSymbolAddress((void**)&xpwh,  g_xpw_h); cudaGetSymbolAddress((void**)&xpwl, g_xpw_l);
    cudaGetSymbolAddress((void**)&outwh, g_outw_h);cudaGetSymbolAddress((void**)&outwl, g_outw_l);
    cudaGetSymbolAddress((void**)&dtwh,  g_dtw_h); cudaGetSymbolAddress((void**)&dtwl, g_dtw_l);

    // weight conversions (every launch — deterministic)
    conv_hl<<<(2*D_INNER*D_MODEL + 255)/256, 256>>>(in_w,  inwh,  inwl,  2*D_INNER*D_MODEL);
    conv_hl<<<(80*D_INNER + 255)/256, 256>>>(xp_w, xpwh, xpwl, 80*D_INNER);
    conv_dtw<<<(D_INNER*64 + 255)/256, 256>>>(dt_w);
    conv_hl<<<(D_MODEL*D_INNER + 255)/256, 256>>>(out_w, outwh, outwl, D_MODEL*D_INNER);

    // 1. LayerNorm -> xn hi/lo
    ln_kernel<<<BL, 256>>>(x, ln_w, ln_b);
    // 2. in_proj (mma.sync): (4096x768)@(3072x768)^T -> g_xr
    tgemm<0><<<dim3(2*D_INNER/128, BL/128), 256>>>(xnh, xnl, inwh, inwl,
                                                   xr, 2*D_INNER, D_MODEL, 2*D_INNER, nullptr);
    // 3. conv + SiLU -> u fp32 + hi/lo
    conv_silu_kernel<<<(BL * D_INNER) / 256, 256>>>(conv_w, conv_b);
    // 4. x_proj (mma.sync): (4096x1536)@(80x1536)^T -> g_dbc (Nvalid=80)
    tgemm<0><<<dim3(1, BL/128), 256>>>(uh, ul, xpwh, xpwl,
                                       dbc, 80, D_INNER, 80, nullptr);
    // 5. dt input conversion + dt_proj (mma.sync, K=64 padded) + bias + softplus
    conv_dti<<<(BL*64 + 255)/256, 256>>>();
    tgemm<1><<<dim3(D_INNER/128, BL/128), 256>>>(dtih, dtil, dtwh, dtwl,
                                                 delta, D_INNER, 64, D_INNER, dt_b);
    // 6-8. chunked selective scan + gate -> yg hi/lo
    scan_pass1<<<dim3(NCHUNK, BB, D_INNER/128), 128>>>(A_log);
    scan_pass2<<<dim3(D_INNER/256, BB), 256>>>(A_log);
    scan_pass3<<<dim3(NCHUNK, BB, D_INNER/128), 128>>>(A_log, Dp);
    // 9. out_proj (mma.sync): (4096x1536)@(768x1536)^T -> out
    tgemm<0><<<dim3(D_MODEL/128, BL/128), 256>>>(ygh, ygl, outwh, outwl,
                                                 out, D_MODEL, D_INNER, D_MODEL, nullptr);
}

// round 17
// speedup vs baseline: 1.6545x; 1.1149x over previous
#include <cuda_runtime.h>
#include <cuda_bf16.h>
#include <math.h>
#include <stdint.h>

// Problem constants
#define D_MODEL 768
#define D_INNER 1536
#define N_STATE 16
#define D_CONV  4
#define DT_RANK 48
#define BB      2
#define LL      2048
#define BL      (BB*LL)        // 4096 rows
#define NCHUNK  16
#define CLEN    (LL/NCHUNK)    // 128

__device__ __forceinline__ uint32_t smem_to_u32(const void* p) {
    uint32_t a;
    asm("{ .reg .u64 t; cvta.to.shared.u64 t, %1; cvt.u32.u64 %0, t; }" : "=r"(a) : "l"(p));
    return a;
}
__device__ __forceinline__ void ldsm_x4(uint32_t& r0, uint32_t& r1, uint32_t& r2, uint32_t& r3,
                                        uint32_t addr) {
    asm volatile("ldmatrix.sync.aligned.m8n8.x4.shared.b16 {%0,%1,%2,%3}, [%4];"
                 : "=r"(r0), "=r"(r1), "=r"(r2), "=r"(r3) : "r"(addr));
}
__device__ __forceinline__ void mma_bf16(float* c, const uint32_t* a, const uint32_t* b) {
    asm volatile("mma.sync.aligned.m16n8k16.row.col.f32.bf16.bf16.f32 "
                 "{%0,%1,%2,%3}, {%4,%5,%6,%7}, {%8,%9}, {%0,%1,%2,%3};"
                 : "+f"(c[0]), "+f"(c[1]), "+f"(c[2]), "+f"(c[3])
                 : "r"(a[0]), "r"(a[1]), "r"(a[2]), "r"(a[3]), "r"(b[0]), "r"(b[1]));
}

// -------- scratch (device globals; no allocation anywhere) --------
__device__ float g_xr   [BL * 2 * D_INNER];          // in_proj out (xin | res) fp32
__device__ float g_xc   [BL * D_INNER];              // conv+silu out u (fp32, for scan)
__device__ float g_dbc  [BL * 80];                   // x_proj out (dt|B|C) fp32
__device__ float g_delta[BL * D_INNER];              // softplus(dt_proj)
__device__ float g_hchunk[BB * NCHUNK * N_STATE * D_INNER];
__device__ float g_S     [BB * NCHUNK * D_INNER];
__device__ float g_hin   [BB * NCHUNK * N_STATE * D_INNER];
// bf16 hi/lo operand buffers (16B aligned for vectorized loads)
__device__ __align__(16) __nv_bfloat16 g_xn_h[BL * D_MODEL],   g_xn_l[BL * D_MODEL];
__device__ __align__(16) __nv_bfloat16 g_u_h [BL * D_INNER],   g_u_l [BL * D_INNER];
__device__ __align__(16) __nv_bfloat16 g_yg_h[BL * D_INNER],   g_yg_l[BL * D_INNER];
__device__ __align__(16) __nv_bfloat16 g_dti_h[BL * 64],       g_dti_l[BL * 64];
__device__ __align__(16) __nv_bfloat16 g_inw_h[2*D_INNER*D_MODEL], g_inw_l[2*D_INNER*D_MODEL];
__device__ __align__(16) __nv_bfloat16 g_xpw_h[80*D_INNER],    g_xpw_l[80*D_INNER];
__device__ __align__(16) __nv_bfloat16 g_dtw_h[D_INNER*64],    g_dtw_l[D_INNER*64];
__device__ __align__(16) __nv_bfloat16 g_outw_h[D_MODEL*D_INNER], g_outw_l[D_MODEL*D_INNER];

__device__ __forceinline__ void f32_hl(float x, __nv_bfloat16& h, __nv_bfloat16& l) {
    h = __float2bfloat16(x);
    l = __float2bfloat16(x - __bfloat162float(h));
}

// ---------------- mma.sync bf16 GEMM: C = A·B^T, 3-term compensation ----------------
// BM=BN=128, BK=32; 256 threads = 8 warps (4 m × 2 n); warp tile 32x64.
// 2-stage cp.async double buffer. A:[M][K] (Ah,Al); B:[N][K] (Bh,Bl); rows>=Nvalid zero.
#define TSTRIDE 40                    // 32 + 8 pad (bf16 elems per smem row)
#define TILE_B  (128 * TSTRIDE * 2)   // 10240 bytes per tile
#define STG_B   (4 * TILE_B)          // 40960 bytes per stage
#define SM_TOTAL (2 * STG_B)          // 81920 bytes

__device__ __forceinline__ void load_tile32_async(uint32_t dst, const __nv_bfloat16* __restrict__ src,
                                                  int ld, int row0, int maxrow, int kc, int tid) {
    #pragma unroll
    for (int it = 0; it < 2; it++) {
        int idx = it * 256 + tid;        // 0..511
        int r = idx >> 2, ch = idx & 3;  // row 0..127, 8-half chunk 0..3
        int ok = (row0 + r < maxrow);
        int rr = ok ? (row0 + r) : 0;    // clamp addr; sz=0 zero-fills dst
        const __nv_bfloat16* g = src + (size_t)rr * ld + kc + ch * 8;
        uint32_t d = dst + (uint32_t)((r * TSTRIDE + ch * 8) * 2);
        int sz = ok ? 16 : 0;
        asm volatile("cp.async.cg.shared.global [%0], [%1], 16, %2;"
                     :: "r"(d), "l"(g), "r"(sz));
    }
}

template<int EPI>   // 0: none, 1: +bias then softplus
__global__ __launch_bounds__(256, 1) void tgemm(const __nv_bfloat16* __restrict__ Ah,
                                                const __nv_bfloat16* __restrict__ Al,
                                                const __nv_bfloat16* __restrict__ Bh,
                                                const __nv_bfloat16* __restrict__ Bl,
                                                float* __restrict__ C, int ldc,
                                                int K, int Nvalid,
                                                const float* __restrict__ bias) {
    extern __shared__ char smem_dyn[];
    const uint32_t sbase = smem_to_u32(smem_dyn);
    const int tid = threadIdx.x;
    const int lane = tid & 31, wid = tid >> 5;
    const int warp_m = wid >> 1;          // 0..3 -> 32-row slab
    const int warp_n = wid & 1;           // 0..1 -> 64-col slab
    const int m0 = blockIdx.y * 128;
    const int n0 = blockIdx.x * 128;

    // ldmatrix per-thread source coordinates
    const int a_row = lane & 15;                 // row within 16-row tile
    const int a_kx  = (lane >> 4);               // 0/1 -> k-subblock (8 halves)
    const int b_row = (lane & 7) + ((lane >> 4) << 3);  // n within 16-col pair
    const int b_kx  = (lane >> 3) & 1;

    float acc[2][8][4];
    #pragma unroll
    for (int mt = 0; mt < 2; mt++)
        #pragma unroll
        for (int nt = 0; nt < 8; nt++)
            #pragma unroll
            for (int i = 0; i < 4; i++) acc[mt][nt][i] = 0.f;

    // prologue: prefetch stage 0
    {
        uint32_t s0 = sbase;
        load_tile32_async(s0 + 0 * TILE_B, Ah, K, m0, 1 << 30, 0, tid);
        load_tile32_async(s0 + 1 * TILE_B, Al, K, m0, 1 << 30, 0, tid);
        load_tile32_async(s0 + 2 * TILE_B, Bh, K, n0, Nvalid, 0, tid);
        load_tile32_async(s0 + 3 * TILE_B, Bl, K, n0, Nvalid, 0, tid);
        asm volatile("cp.async.commit_group;" ::: "memory");
    }

    const int nk = K / 32;
    for (int t = 0; t < nk; t++) {
        const int cur = t & 1;
        if (t + 1 < nk) {
            uint32_t sn = sbase + (uint32_t)((cur ^ 1) * STG_B);
            int kc = (t + 1) * 32;
            load_tile32_async(sn + 0 * TILE_B, Ah, K, m0, 1 << 30, kc, tid);
            load_tile32_async(sn + 1 * TILE_B, Al, K, m0, 1 << 30, kc, tid);
            load_tile32_async(sn + 2 * TILE_B, Bh, K, n0, Nvalid, kc, tid);
            load_tile32_async(sn + 3 * TILE_B, Bl, K, n0, Nvalid, kc, tid);
            asm volatile("cp.async.commit_group;" ::: "memory");
            asm volatile("cp.async.wait_group 1;" ::: "memory");
        } else {
            asm volatile("cp.async.wait_group 0;" ::: "memory");
        }
        __syncthreads();

        const uint32_t cAH = sbase + (uint32_t)(cur * STG_B);
        const uint32_t cAL = cAH + TILE_B;
        const uint32_t cBH = cAH + 2 * TILE_B;
        const uint32_t cBL = cAH + 3 * TILE_B;

        #pragma unroll
        for (int ks = 0; ks < 2; ks++) {
            const int kbase = ks * 16;
            uint32_t ah[2][4], al[2][4];
            #pragma unroll
            for (int mt = 0; mt < 2; mt++) {
                uint32_t off = (uint32_t)(((warp_m * 32 + mt * 16 + a_row) * TSTRIDE
                                           + kbase + a_kx * 8) * 2);
                ldsm_x4(ah[mt][0], ah[mt][1], ah[mt][2], ah[mt][3], cAH + off);
                ldsm_x4(al[mt][0], al[mt][1], al[mt][2], al[mt][3], cAL + off);
            }
            uint32_t bh[8][2], bl[8][2];
            #pragma unroll
            for (int ntp = 0; ntp < 4; ntp++) {   // n-tile pairs (16 cols each)
                uint32_t off = (uint32_t)(((warp_n * 64 + ntp * 16 + b_row) * TSTRIDE
                                           + kbase + b_kx * 8) * 2);
                ldsm_x4(bh[2*ntp][0], bh[2*ntp][1], bh[2*ntp+1][0], bh[2*ntp+1][1], cBH + off);
                ldsm_x4(bl[2*ntp][0], bl[2*ntp][1], bl[2*ntp+1][0], bl[2*ntp+1][1], cBL + off);
            }
            #pragma unroll
            for (int mt = 0; mt < 2; mt++)
                #pragma unroll
                for (int nt = 0; nt < 8; nt++) {
                    mma_bf16(acc[mt][nt], ah[mt], bh[nt]);
                    mma_bf16(acc[mt][nt], ah[mt], bl[nt]);
                    mma_bf16(acc[mt][nt], al[mt], bh[nt]);
                }
        }
        __syncthreads();   // protect cur-stage buffers before t+1 issues into them
    }

    // Epilogue: fragment layout c0,c1=(r, 2c/2c+1), c2,c3=(r+8, ...)
    const int r_off = lane >> 2;
    const int c_off = (lane & 3) * 2;
    #pragma unroll
    for (int mt = 0; mt < 2; mt++) {
        #pragma unroll
        for (int nt = 0; nt < 8; nt++) {
            int row_g = m0 + warp_m * 32 + mt * 16 + r_off;
            int col_g = n0 + warp_n * 64 + nt * 8 + c_off;
            if (col_g < Nvalid) {
                float v0 = acc[mt][nt][0], v1 = acc[mt][nt][1];
                float v2 = acc[mt][nt][2], v3 = acc[mt][nt][3];
                if (EPI == 1) {
                    float bv0 = bias[col_g], bv1 = bias[col_g + 1];
                    v0 += bv0; v1 += bv1; v2 += bv0; v3 += bv1;
                    v0 = (v0 > 20.f) ? v0 : log1pf(__expf(v0));
                    v1 = (v1 > 20.f) ? v1 : log1pf(__expf(v1));
                    v2 = (v2 > 20.f) ? v2 : log1pf(__expf(v2));
                    v3 = (v3 > 20.f) ? v3 : log1pf(__expf(v3));
                }
                *(float2*)(C + (size_t)row_g * ldc + col_g)       = make_float2(v0, v1);
                *(float2*)(C + (size_t)(row_g + 8) * ldc + col_g) = make_float2(v2, v3);
            }
        }
    }
}

// ---------------- LayerNorm -> bf16 hi/lo ----------------
__device__ __forceinline__ float block_sum_768(float v, float* sh) {
    int lane = threadIdx.x & 31, w = threadIdx.x >> 5;
    #pragma unroll
    for (int o = 16; o > 0; o >>= 1) v += __shfl_xor_sync(0xffffffffu, v, o);
    if (lane == 0) sh[w] = v;
    __syncthreads();
    if (threadIdx.x == 0) {
        float s = 0.f;
        #pragma unroll
        for (int i = 0; i < 8; i++) s += sh[i];
        sh[8] = s;
    }
    __syncthreads();
    float r = sh[8];
    __syncthreads();
    return r;
}

__global__ __launch_bounds__(256) void ln_kernel(const float* __restrict__ x,
                                                 const float* __restrict__ w,
                                                 const float* __restrict__ b) {
    __shared__ float sh[9];
    int row = blockIdx.x;
    const float* xp = x + (size_t)row * D_MODEL;
    int t = threadIdx.x;
    float v0 = xp[t], v1 = xp[t + 256], v2 = xp[t + 512];
    float mu = block_sum_768(v0 + v1 + v2, sh) * (1.f / 768.f);
    float d0 = v0 - mu, d1 = v1 - mu, d2 = v2 - mu;
    float var = block_sum_768(d0*d0 + d1*d1 + d2*d2, sh) * (1.f / 768.f);
    float inv = rsqrtf(var + 1e-5f);
    size_t o = (size_t)row * D_MODEL;
    #pragma unroll
    for (int j = 0; j < 3; j++) {
        int c = t + j * 256;
        float dv = (j == 0 ? d0 : (j == 1 ? d1 : d2));
        float v = dv * inv * w[c] + b[c];
        f32_hl(v, g_xn_h[o + c], g_xn_l[o + c]);
    }
}

// ---------------- fp32 -> bf16 hi/lo (generic, for weights) ----------------
__global__ __launch_bounds__(256) void conv_hl(const float* __restrict__ src,
                                               __nv_bfloat16* __restrict__ dh,
                                               __nv_bfloat16* __restrict__ dl, int n) {
    int i = blockIdx.x * 256 + threadIdx.x;
    if (i < n) f32_hl(src[i], dh[i], dl[i]);
}

// dt input: g_dbc cols 0..47 -> [BL][64] hi/lo, cols 48..63 zero
__global__ __launch_bounds__(256) void conv_dti() {
    int i = blockIdx.x * 256 + threadIdx.x;   // over BL*64
    int r = i >> 6, c = i & 63;
    float v = (c < DT_RANK) ? g_dbc[r * 80 + c] : 0.f;
    f32_hl(v, g_dti_h[i], g_dti_l[i]);
}
// dt_w: [1536][48] -> [1536][64] hi/lo padded
__global__ __launch_bounds__(256) void conv_dtw(const float* __restrict__ w) {
    int i = blockIdx.x * 256 + threadIdx.x;   // over 1536*64
    int r = i >> 6, c = i & 63;
    float v = (c < DT_RANK) ? w[r * DT_RANK + c] : 0.f;
    f32_hl(v, g_dtw_h[i], g_dtw_l[i]);
}

// ---------------- depthwise causal conv(k=4) + bias + SiLU -> u fp32 + hi/lo ----------------
__global__ __launch_bounds__(256) void conv_silu_kernel(const float* __restrict__ w,
                                                        const float* __restrict__ cb) {
    int idx = blockIdx.x * 256 + threadIdx.x;   // over BL*D_INNER
    int d = idx % D_INNER;
    int row = idx / D_INNER;
    int l = row & (LL - 1);
    const float* xin = g_xr + (size_t)row * (2 * D_INNER) + d;
    float acc = cb[d];
    float4 wv = *(const float4*)(w + d * 4);
    if (l >= 3) acc += wv.x * xin[-3 * 2 * D_INNER];
    if (l >= 2) acc += wv.y * xin[-2 * 2 * D_INNER];
    if (l >= 1) acc += wv.z * xin[-1 * 2 * D_INNER];
    acc += wv.w * xin[0];
    float u = __fdividef(acc, 1.f + __expf(-acc));
    size_t o = (size_t)row * D_INNER + d;
    g_xc[o] = u;
    f32_hl(u, g_u_h[o], g_u_l[o]);
}

// ---------------- selective scan (chunked, 3 passes) ----------------
__global__ __launch_bounds__(128) void scan_pass1(const float* __restrict__ A_log) {
    __shared__ float sB[CLEN * N_STATE];
    int c = blockIdx.x, b = blockIdx.y;
    int d = blockIdx.z * 128 + threadIdx.x;
    int rowbase = b * LL + c * CLEN;
    for (int i = threadIdx.x; i < CLEN * N_STATE; i += 128) {
        int l = i >> 4, n = i & 15;
        sB[i] = g_dbc[(size_t)(rowbase + l) * 80 + DT_RANK + n];
    }
    __syncthreads();
    float Areg[N_STATE];
    #pragma unroll
    for (int n = 0; n < N_STATE; n++) Areg[n] = -__expf(A_log[d * N_STATE + n]);
    float h[N_STATE];
    #pragma unroll
    for (int n = 0; n < N_STATE; n++) h[n] = 0.f;
    float S = 0.f;
    for (int l = 0; l < CLEN; l++) {
        size_t off = (size_t)(rowbase + l) * D_INNER + d;
        float dl = g_delta[off];
        float ul = g_xc[off];
        S += dl;
        float du = dl * ul;
        const float* bl = sB + l * N_STATE;
        #pragma unroll
        for (int n = 0; n < N_STATE; n++)
            h[n] = __expf(dl * Areg[n]) * h[n] + du * bl[n];
    }
    size_t base = (size_t)((b * NCHUNK + c) * N_STATE) * D_INNER + d;
    #pragma unroll
    for (int n = 0; n < N_STATE; n++) g_hchunk[base + (size_t)n * D_INNER] = h[n];
    g_S[(size_t)(b * NCHUNK + c) * D_INNER + d] = S;
}

__global__ __launch_bounds__(256) void scan_pass2(const float* __restrict__ A_log) {
    int d = blockIdx.x * 256 + threadIdx.x;
    int b = blockIdx.y;
    float Areg[N_STATE];
    #pragma unroll
    for (int n = 0; n < N_STATE; n++) Areg[n] = -__expf(A_log[d * N_STATE + n]);
    float h[N_STATE];
    #pragma unroll
    for (int n = 0; n < N_STATE; n++) h[n] = 0.f;
    for (int c = 0; c < NCHUNK; c++) {
        size_t base = (size_t)((b * NCHUNK + c) * N_STATE) * D_INNER + d;
        #pragma unroll
        for (int n = 0; n < N_STATE; n++) g_hin[base + (size_t)n * D_INNER] = h[n];
        float S = g_S[(size_t)(b * NCHUNK + c) * D_INNER + d];
        #pragma unroll
        for (int n = 0; n < N_STATE; n++)
            h[n] = __expf(S * Areg[n]) * h[n] + g_hchunk[base + (size_t)n * D_INNER];
    }
}

__global__ __launch_bounds__(128) void scan_pass3(const float* __restrict__ A_log,
                                                  const float* __restrict__ Dp) {
    __shared__ float sBC[CLEN * 2 * N_STATE];
    int c = blockIdx.x, b = blockIdx.y;
    int d = blockIdx.z * 128 + threadIdx.x;
    int rowbase = b * LL + c * CLEN;
    for (int i = threadIdx.x; i < CLEN * 2 * N_STATE; i += 128) {
        int l = i >> 5, j = i & 31;
        sBC[i] = g_dbc[(size_t)(rowbase + l) * 80 + DT_RANK + j];
    }
    __syncthreads();
    float Areg[N_STATE];
    #pragma unroll
    for (int n = 0; n < N_STATE; n++) Areg[n] = -__expf(A_log[d * N_STATE + n]);
    float h[N_STATE];
    size_t hbase = (size_t)((b * NCHUNK + c) * N_STATE) * D_INNER + d;
    #pragma unroll
    for (int n = 0; n < N_STATE; n++) h[n] = g_hin[hbase + (size_t)n * D_INNER];
    float Dd = Dp[d];
    for (int l = 0; l < CLEN; l++) {
        size_t off = (size_t)(rowbase + l) * D_INNER + d;
        float dl = g_delta[off];
        float ul = g_xc[off];
        float du = dl * ul;
        const float* bl = sBC + l * 2 * N_STATE;
        float y = 0.f;
        #pragma unroll
        for (int n = 0; n < N_STATE; n++) {
            h[n] = __expf(dl * Areg[n]) * h[n] + du * bl[n];
            y += h[n] * bl[N_STATE + n];
        }
        y += ul * Dd;
        int row = rowbase + l;
        float r = g_xr[(size_t)row * (2 * D_INNER) + D_INNER + d];
        float sr = __fdividef(r, 1.f + __expf(-r));
        f32_hl(y * sr, g_yg_h[off], g_yg_l[off]);
    }
}

// ---------------- launch ----------------
extern "C" void kernel_launch(void* const* d_in, const int* in_sizes, int n_in,
                              void* d_out, int out_size) {
    const float* x      = (const float*)d_in[0];
    const float* ln_w   = (const float*)d_in[1];
    const float* ln_b   = (const float*)d_in[2];
    const float* in_w   = (const float*)d_in[3];   // (3072, 768)
    const float* conv_w = (const float*)d_in[4];
    const float* conv_b = (const float*)d_in[5];
    const float* xp_w   = (const float*)d_in[6];   // (80, 1536)
    const float* dt_w   = (const float*)d_in[7];   // (1536, 48)
    const float* dt_b   = (const float*)d_in[8];
    const float* A_log  = (const float*)d_in[9];
    const float* Dp     = (const float*)d_in[10];
    const float* out_w  = (const float*)d_in[11];  // (768, 1536)
    float* out = (float*)d_out;

    // unconditional; capture-safe, not stream-ordered
    cudaFuncSetAttribute(tgemm<0>, cudaFuncAttributeMaxDynamicSharedMemorySize, SM_TOTAL);
    cudaFuncSetAttribute(tgemm<1>, cudaFuncAttributeMaxDynamicSharedMemorySize, SM_TOTAL);

    float *xr, *dbc, *delta;
    __nv_bfloat16 *xnh, *xnl, *uh, *ul, *ygh, *ygl, *dtih, *dtil;
    __nv_bfloat16 *inwh, *inwl, *xpwh, *xpwl, *outwh, *outwl, *dtwh, *dtwl;
    cudaGetSymbolAddress((void**)&xr,    g_xr);
    cudaGetSymbolAddress((void**)&dbc,   g_dbc);
    cudaGetSymbolAddress((void**)&delta, g_delta);
    cudaGetSymbolAddress((void**)&xnh,   g_xn_h);  cudaGetSymbolAddress((void**)&xnl, g_xn_l);
    cudaGetSymbolAddress((void**)&uh,    g_u_h);   cudaGetSymbolAddress((void**)&ul,  g_u_l);
    cudaGetSymbolAddress((void**)&ygh,   g_yg_h);  cudaGetSymbolAddress((void**)&ygl, g_yg_l);
    cudaGetSymbolAddress((void**)&dtih,  g_dti_h); cudaGetSymbolAddress((void**)&dtil, g_dti_l);
    cudaGetSymbolAddress((void**)&inwh,  g_inw_h); cudaGetSymbolAddress((void**)&inwl, g_inw_l);
    cudaGetSymbolAddress((void**)&xpwh,  g_xpw_h); cudaGetSymbolAddress((void**)&xpwl, g_xpw_l);
    cudaGetSymbolAddress((void**)&outwh, g_outw_h);cudaGetSymbolAddress((void**)&outwl, g_outw_l);
    cudaGetSymbolAddress((void**)&dtwh,  g_dtw_h); cudaGetSymbolAddress((void**)&dtwl, g_dtw_l);

    // weight conversions (every launch — deterministic)
    conv_hl<<<(2*D_INNER*D_MODEL + 255)/256, 256>>>(in_w,  inwh,  inwl,  2*D_INNER*D_MODEL);
    conv_hl<<<(80*D_INNER + 255)/256, 256>>>(xp_w, xpwh, xpwl, 80*D_INNER);
    conv_dtw<<<(D_INNER*64 + 255)/256, 256>>>(dt_w);
    conv_hl<<<(D_MODEL*D_INNER + 255)/256, 256>>>(out_w, outwh, outwl, D_MODEL*D_INNER);

    // 1. LayerNorm -> xn hi/lo
    ln_kernel<<<BL, 256>>>(x, ln_w, ln_b);
    // 2. in_proj (mma.sync): (4096x768)@(3072x768)^T -> g_xr
    tgemm<0><<<dim3(2*D_INNER/128, BL/128), 256, SM_TOTAL>>>(xnh, xnl, inwh, inwl,
                                                             xr, 2*D_INNER, D_MODEL, 2*D_INNER, nullptr);
    // 3. conv + SiLU -> u fp32 + hi/lo
    conv_silu_kernel<<<(BL * D_INNER) / 256, 256>>>(conv_w, conv_b);
    // 4. x_proj (mma.sync): (4096x1536)@(80x1536)^T -> g_dbc (Nvalid=80)
    tgemm<0><<<dim3(1, BL/128), 256, SM_TOTAL>>>(uh, ul, xpwh, xpwl,
                                                 dbc, 80, D_INNER, 80, nullptr);
    // 5. dt input conversion + dt_proj (mma.sync, K=64 padded) + bias + softplus
    conv_dti<<<(BL*64 + 255)/256, 256>>>();
    tgemm<1><<<dim3(D_INNER/128, BL/128), 256, SM_TOTAL>>>(dtih, dtil, dtwh, dtwl,
                                                           delta, D_INNER, 64, D_INNER, dt_b);
    // 6-8. chunked selective scan + gate -> yg hi/lo
    scan_pass1<<<dim3(NCHUNK, BB, D_INNER/128), 128>>>(A_log);
    scan_pass2<<<dim3(D_INNER/256, BB), 256>>>(A_log);
    scan_pass3<<<dim3(NCHUNK, BB, D_INNER/128), 128>>>(A_log, Dp);
    // 9. out_proj (mma.sync): (4096x1536)@(768x1536)^T -> out
    tgemm<0><<<dim3(D_MODEL/128, BL/128), 256, SM_TOTAL>>>(ygh, ygl, outwh, outwl,
                                                           out, D_MODEL, D_INNER, D_MODEL, nullptr);
}